// round 17
// baseline (speedup 1.0000x reference)
#include <cuda_runtime.h>
#include <math.h>

#define NN 50000
#define EE 800000
#define FIN 256
#define CC 32
#define HH 4
#define HCC 128
#define LEPS 1e-5f
#define SLOPE 0.2f

// ---------------- scratch (no allocs allowed) ----------------
__device__ float d_h[NN * CC];        // current node features
__device__ float d_xl[NN * HCC];      // lin_l(h)
__device__ float d_xr[NN * HCC];      // lin_r(h)
__device__ float d_gat[NN * HCC];     // GAT aggregation output
__device__ double d_red[2];           // global sum / sumsq (self-resetting)
__device__ unsigned int d_ctr;        // block-completion counter (self-resetting)
__device__ float d_stats[2];          // mu, rstd for graph-LN
// CSR by destination
__device__ int  d_cnt[NN];            // zero at load; k_scan re-zeros for replay
__device__ int  d_rowoff[NN + 1];
__device__ int  d_cursor[NN];
__device__ int2 d_csr[EE];            // (src, ea as bits)

// ---------------- helpers ----------------
__device__ __forceinline__ float wsum(float v) {
    #pragma unroll
    for (int o = 16; o; o >>= 1) v += __shfl_xor_sync(0xFFFFFFFFu, v, o);
    return v;
}
__device__ __forceinline__ float lrelu(float z) {
    return z > 0.0f ? z : SLOPE * z;
}

// ---------------- CSR build ----------------
__global__ void k_hist(const int* __restrict__ dst) {
    int e = blockIdx.x * blockDim.x + threadIdx.x;
    if (e < EE) atomicAdd(&d_cnt[dst[e]], 1);
}
// single block, 1024 threads: exclusive scan of d_cnt -> d_rowoff, d_cursor.
// Re-zeros d_cnt so the next kernel_launch call (graph replay) starts clean.
__global__ void k_scan() {
    __shared__ int wsum_ex[32];
    __shared__ int s_total;
    int lane = threadIdx.x & 31, wid = threadIdx.x >> 5;
    int carry = 0;
    const int CH = (NN + 1023) / 1024;
    for (int c = 0; c < CH; c++) {
        int i = c * 1024 + threadIdx.x;
        int v = (i < NN) ? d_cnt[i] : 0;
        if (i < NN) d_cnt[i] = 0;   // reset for next launch / graph replay
        int inc = v;
        #pragma unroll
        for (int o = 1; o < 32; o <<= 1) {
            int t = __shfl_up_sync(0xFFFFFFFFu, inc, o);
            if (lane >= o) inc += t;
        }
        if (lane == 31) wsum_ex[wid] = inc;
        __syncthreads();
        if (wid == 0) {
            int w = wsum_ex[lane];
            int wi = w;
            #pragma unroll
            for (int o = 1; o < 32; o <<= 1) {
                int t = __shfl_up_sync(0xFFFFFFFFu, wi, o);
                if (lane >= o) wi += t;
            }
            wsum_ex[lane] = wi - w;
            if (lane == 31) s_total = wi;
        }
        __syncthreads();
        int excl = carry + wsum_ex[wid] + (inc - v);
        if (i < NN) { d_rowoff[i] = excl; d_cursor[i] = excl; }
        carry += s_total;
        __syncthreads();
    }
    if (threadIdx.x == 0) d_rowoff[NN] = EE;
}
__global__ void k_scatter(const int* __restrict__ src, const int* __restrict__ dst,
                          const float* __restrict__ ea) {
    int e = blockIdx.x * blockDim.x + threadIdx.x;
    if (e >= EE) return;
    int d = dst[e];
    int pos = atomicAdd(&d_cursor[d], 1);
    d_csr[pos] = make_int2(src[e], __float_as_int(ea[e]));
}

// ---------------- K1: embed GEMM + node LN + ReLU + JK init ----------------
// 256 threads = 8 warps; warp handles 4 nodes sequentially.
// x-row staged in smem via coalesced LDG.128/STS.128, read back as broadcast LDS.128.
// W transposed+padded in smem. Zero shuffles in mainloop.
__global__ void __launch_bounds__(256)
k_embed(const float* __restrict__ x, const float* __restrict__ W,
        const float* __restrict__ b, const float* __restrict__ lw,
        const float* __restrict__ lb, float* __restrict__ out) {
    __shared__ float sWT[CC][FIN + 4];   // [col][k], padded (33 KB)
    __shared__ float sX[8][FIN];         // per-warp x-row buffer (8 KB)
    int tid = threadIdx.x;
    for (int i = tid; i < FIN * CC; i += 256) {
        int k = i >> 5, col = i & 31;
        sWT[col][k] = W[i];              // W[k*CC+col]
    }
    __syncthreads();
    int lane = tid & 31;
    int w = tid >> 5;
    int n0 = blockIdx.x * 32 + w * 4;

    float bv = b[lane], lwv = lw[lane], lbv = lb[lane];

    // prefetch first row into registers (coalesced: lane covers 2 float4 slices)
    float4 rA = make_float4(0.f, 0.f, 0.f, 0.f), rB = rA;
    if (n0 < NN) {
        const float* row = x + (size_t)n0 * FIN;
        rA = __ldg((const float4*)(row) + lane);
        rB = __ldg((const float4*)(row) + 32 + lane);
    }

    #pragma unroll
    for (int m = 0; m < 4; m++) {
        int n = n0 + m;
        if (n >= NN) break;   // warp-uniform
        *(float4*)&sX[w][lane * 4] = rA;
        *(float4*)&sX[w][128 + lane * 4] = rB;
        __syncwarp();
        if (m < 3 && n + 1 < NN) {
            const float* row = x + (size_t)(n + 1) * FIN;
            rA = __ldg((const float4*)(row) + lane);
            rB = __ldg((const float4*)(row) + 32 + lane);
        }
        float acc = bv;
        #pragma unroll 8
        for (int kq = 0; kq < FIN / 4; kq++) {
            float4 xv = *(const float4*)&sX[w][kq * 4];       // broadcast
            float4 wv = *(const float4*)&sWT[lane][kq * 4];   // conflict-free
            acc += xv.x * wv.x + xv.y * wv.y + xv.z * wv.z + xv.w * wv.w;
        }
        __syncwarp();
        float mu = wsum(acc) * (1.0f / CC);
        float c = acc - mu;
        float var = wsum(c * c) * (1.0f / CC);
        float y = c * rsqrtf(var + LEPS) * lwv + lbv;
        y = fmaxf(y, 0.0f);
        d_h[n * CC + lane] = y;
        out[n * CC + lane] = y;   // JK running max init
    }
}

// ---------------- K2: xl = h@Wl+bl ; xr = h@Wr+br ----------------
// 128 threads: thread owns output col tid with weight columns in registers; 32 nodes/block
__global__ void k_linlr(const float* __restrict__ Wl, const float* __restrict__ bl,
                        const float* __restrict__ Wr, const float* __restrict__ br) {
    __shared__ float4 sh4[32 * 8];   // 32 nodes x 32 feats
    int tid = threadIdx.x;
    float rWl[CC], rWr[CC];
    #pragma unroll
    for (int k = 0; k < CC; k++) {
        rWl[k] = Wl[k * HCC + tid];
        rWr[k] = Wr[k * HCC + tid];
    }
    int base = blockIdx.x * 32;
    for (int i = tid; i < 32 * 8; i += 128) {
        int n = base + (i >> 3);
        sh4[i] = (n < NN) ? *(const float4*)&d_h[n * CC + (i & 7) * 4]
                          : make_float4(0.f, 0.f, 0.f, 0.f);
    }
    __syncthreads();
    float blv = bl[tid], brv = br[tid];
    for (int j = 0; j < 32; j++) {
        int n = base + j;
        if (n >= NN) break;
        float al = blv, ar = brv;
        #pragma unroll
        for (int k4 = 0; k4 < 8; k4++) {
            float4 h4 = sh4[j * 8 + k4];
            al += h4.x * rWl[k4 * 4 + 0]; ar += h4.x * rWr[k4 * 4 + 0];
            al += h4.y * rWl[k4 * 4 + 1]; ar += h4.y * rWr[k4 * 4 + 1];
            al += h4.z * rWl[k4 * 4 + 2]; ar += h4.z * rWr[k4 * 4 + 2];
            al += h4.w * rWl[k4 * 4 + 3]; ar += h4.w * rWr[k4 * 4 + 3];
        }
        d_xl[n * HCC + tid] = al;
        d_xr[n * HCC + tid] = ar;
    }
}

// ---------------- K3: fused GATv2 aggregation + graph-LN reduction ----------------
// warp per dst node (grid exactly NN/8 blocks of 256 => no tail warps).
// Softmax stabilized with the CONSTANT self-loop logit p: alpha = exp(q-p)/sum.
// Depth-2 rotating-register software pipeline (the proven configuration).
__global__ void k_gat(const float* __restrict__ We, const float* __restrict__ att,
                      const float* __restrict__ gb) {
    int tid = threadIdx.x;
    int lane = tid & 31;
    int w = tid >> 5;
    int n = blockIdx.x * 8 + w;

    float4 xr4  = *(const float4*)&d_xr[(size_t)n * HCC + lane * 4];
    float4 xls  = *(const float4*)&d_xl[(size_t)n * HCC + lane * 4];
    float4 att4 = *(const float4*)&att[lane * 4];
    float4 We4  = *(const float4*)&We[lane * 4];

    // self loop logit p (edge_attr = 0)
    float p;
    {
        float zx = lrelu(xls.x + xr4.x);
        float zy = lrelu(xls.y + xr4.y);
        float zz = lrelu(xls.z + xr4.z);
        float zw = lrelu(xls.w + xr4.w);
        p = zx * att4.x + zy * att4.y + zz * att4.z + zw * att4.w;
        p += __shfl_xor_sync(0xFFFFFFFFu, p, 1);
        p += __shfl_xor_sync(0xFFFFFFFFu, p, 2);
        p += __shfl_xor_sync(0xFFFFFFFFu, p, 4);
    }
    float s = 1.0f;       // exp(p-p)
    float4 acc = xls;     // self message

    int beg = __ldg(&d_rowoff[n]), end = __ldg(&d_rowoff[n + 1]);

    // depth-2 software pipeline
    int2 e0 = make_int2(0, 0), e1 = make_int2(0, 0);
    float4 x0 = make_float4(0.f, 0.f, 0.f, 0.f), x1 = x0;
    if (beg < end) {
        e0 = __ldg(&d_csr[beg]);
        x0 = *(const float4*)&d_xl[(size_t)e0.x * HCC + lane * 4];
    }
    if (beg + 1 < end) {
        e1 = __ldg(&d_csr[beg + 1]);
        x1 = *(const float4*)&d_xl[(size_t)e1.x * HCC + lane * 4];
    }
    for (int k = beg; k < end; k++) {
        int2 ec = e0;
        float4 xc = x0;
        e0 = e1; x0 = x1;
        if (k + 2 < end) {
            e1 = __ldg(&d_csr[k + 2]);
            x1 = *(const float4*)&d_xl[(size_t)e1.x * HCC + lane * 4];
        }
        float eaf = __int_as_float(ec.y);
        float zx = lrelu(xc.x + xr4.x + eaf * We4.x);
        float zy = lrelu(xc.y + xr4.y + eaf * We4.y);
        float zz = lrelu(xc.z + xr4.z + eaf * We4.z);
        float zw = lrelu(xc.w + xr4.w + eaf * We4.w);
        float q = zx * att4.x + zy * att4.y + zz * att4.z + zw * att4.w;
        q += __shfl_xor_sync(0xFFFFFFFFu, q, 1);
        q += __shfl_xor_sync(0xFFFFFFFFu, q, 2);
        q += __shfl_xor_sync(0xFFFFFFFFu, q, 4);
        float ex = __expf(q - p);
        s += ex;
        acc.x += ex * xc.x;
        acc.y += ex * xc.y;
        acc.z += ex * xc.z;
        acc.w += ex * xc.w;
    }
    float inv = 1.0f / s;
    float4 o;
    o.x = acc.x * inv; o.y = acc.y * inv; o.z = acc.z * inv; o.w = acc.w * inv;
    *(float4*)&d_gat[(size_t)n * HCC + lane * 4] = o;

    // ---- fused graph-LN reduction (over o + gb) ----
    float4 gb4 = *(const float4*)&gb[lane * 4];
    float vx = o.x + gb4.x, vy = o.y + gb4.y, vz = o.z + gb4.z, vw = o.w + gb4.w;
    double s0 = (double)vx + (double)vy + (double)vz + (double)vw;
    double s1 = (double)vx * vx + (double)vy * vy + (double)vz * vz + (double)vw * vw;
    #pragma unroll
    for (int off = 16; off; off >>= 1) {
        s0 += __shfl_xor_sync(0xFFFFFFFFu, s0, off);
        s1 += __shfl_xor_sync(0xFFFFFFFFu, s1, off);
    }
    __shared__ double sh0[8], sh1[8];
    if (lane == 0) { sh0[w] = s0; sh1[w] = s1; }
    __syncthreads();
    if (w == 0) {
        s0 = (lane < 8) ? sh0[lane] : 0.0;
        s1 = (lane < 8) ? sh1[lane] : 0.0;
        #pragma unroll
        for (int off = 4; off; off >>= 1) {
            s0 += __shfl_xor_sync(0xFFFFFFFFu, s0, off);
            s1 += __shfl_xor_sync(0xFFFFFFFFu, s1, off);
        }
        if (lane == 0) {
            atomicAdd(&d_red[0], s0);
            atomicAdd(&d_red[1], s1);
            __threadfence();
            unsigned int t = atomicAdd(&d_ctr, 1u);
            if (t == gridDim.x - 1) {
                double inv2 = 1.0 / ((double)NN * (double)HCC);
                double mu = d_red[0] * inv2;
                double var = d_red[1] * inv2 - mu * mu;
                d_stats[0] = (float)mu;
                d_stats[1] = (float)(1.0 / sqrt(var + 1e-5));
                d_red[0] = 0.0;      // self-reset for next launch / replay
                d_red[1] = 0.0;
                d_ctr = 0u;
            }
        }
    }
}

// ---------------- K8: graph-LN apply + ReLU + 128->32 GEMM + node LN + ReLU + JK max ----------------
// MIO-lean: lw transposed+padded in smem, v staged per-warp via STS.128,
// mainloop = broadcast LDS.128 + conflict-free LDS.128, zero shuffles (embed pattern).
__global__ void __launch_bounds__(256)
k_lin2(const float* __restrict__ gb, const float* __restrict__ l1w,
       const float* __restrict__ l1b, const float* __restrict__ lw,
       const float* __restrict__ lb, const float* __restrict__ l2w,
       const float* __restrict__ l2b, float* __restrict__ out) {
    __shared__ float s_lwT[CC][HCC + 4];   // [col][k], padded (16.9 KB)
    __shared__ float sV[8][HCC];           // per-warp v buffer (4 KB)
    int tid = threadIdx.x;
    for (int i = tid; i < HCC * CC; i += 256) {
        int k = i >> 5, col = i & 31;
        s_lwT[col][k] = lw[k * CC + col];
    }
    __syncthreads();
    int lane = tid & 31;
    int w = tid >> 5;
    int n = blockIdx.x * 8 + w;
    float mu = d_stats[0], rstd = d_stats[1];
    float4 g4  = *(const float4*)&d_gat[(size_t)n * HCC + lane * 4];
    float4 gb4 = *(const float4*)&gb[lane * 4];
    float4 w14 = *(const float4*)&l1w[lane * 4];
    float4 b14 = *(const float4*)&l1b[lane * 4];
    float4 v4;
    v4.x = fmaxf((g4.x + gb4.x - mu) * rstd * w14.x + b14.x, 0.0f);
    v4.y = fmaxf((g4.y + gb4.y - mu) * rstd * w14.y + b14.y, 0.0f);
    v4.z = fmaxf((g4.z + gb4.z - mu) * rstd * w14.z + b14.z, 0.0f);
    v4.w = fmaxf((g4.w + gb4.w - mu) * rstd * w14.w + b14.w, 0.0f);
    *(float4*)&sV[w][lane * 4] = v4;
    __syncwarp();
    float acc = lb[lane];
    #pragma unroll 8
    for (int kq = 0; kq < HCC / 4; kq++) {
        float4 xv = *(const float4*)&sV[w][kq * 4];          // broadcast
        float4 wv = *(const float4*)&s_lwT[lane][kq * 4];    // conflict-free
        acc += xv.x * wv.x + xv.y * wv.y + xv.z * wv.z + xv.w * wv.w;
    }
    float m2 = wsum(acc) * (1.0f / CC);
    float c = acc - m2;
    float var = wsum(c * c) * (1.0f / CC);
    float y = c * rsqrtf(var + LEPS) * l2w[lane] + l2b[lane];
    y = fmaxf(y, 0.0f);
    d_h[n * CC + lane] = y;
    out[n * CC + lane] = fmaxf(out[n * CC + lane], y);   // JK max
}

// ---------------- host ----------------
extern "C" void kernel_launch(void* const* d_in, const int* in_sizes, int n_in,
                              void* d_out, int out_size) {
    const float* x     = (const float*)d_in[0];
    const int*   ei    = (const int*)d_in[1];
    const float* ea    = (const float*)d_in[2];
    const float* W_emb = (const float*)d_in[3];
    const float* b_emb = (const float*)d_in[4];
    const float* ln0w  = (const float*)d_in[5];
    const float* ln0b  = (const float*)d_in[6];
    const float* Wl    = (const float*)d_in[7];
    const float* bl    = (const float*)d_in[8];
    const float* Wr    = (const float*)d_in[9];
    const float* br    = (const float*)d_in[10];
    const float* We    = (const float*)d_in[11];
    const float* att   = (const float*)d_in[12];
    const float* gatb  = (const float*)d_in[13];
    const float* ln1w  = (const float*)d_in[14];
    const float* ln1b  = (const float*)d_in[15];
    const float* linw  = (const float*)d_in[16];
    const float* linb  = (const float*)d_in[17];
    const float* ln2w  = (const float*)d_in[18];
    const float* ln2b  = (const float*)d_in[19];

    const int* src = ei;
    const int* dst = ei + EE;
    float* out = (float*)d_out;

    const int gatBlocks   = NN / 8;            // 6250, exact
    const int embedBlocks = (NN + 31) / 32;    // 1563 (warp does 4 nodes)

    // CSR build (reused by both layers); k_scan self-zeros d_cnt for replay
    k_hist<<<(EE + 255) / 256, 256>>>(dst);
    k_scan<<<1, 1024>>>();
    k_scatter<<<(EE + 255) / 256, 256>>>(src, dst, ea);

    k_embed<<<embedBlocks, 256>>>(x, W_emb, b_emb, ln0w, ln0b, out);

    for (int l = 0; l < 2; l++) {
        const float* Wl_l  = Wl + l * CC * HCC;
        const float* bl_l  = bl + l * HCC;
        const float* Wr_l  = Wr + l * CC * HCC;
        const float* br_l  = br + l * HCC;
        const float* We_l  = We + l * HCC;
        const float* att_l = att + l * HH * CC;
        const float* gb_l  = gatb + l * HCC;
        const float* l1w_l = ln1w + l * HCC;
        const float* l1b_l = ln1b + l * HCC;
        const float* lw_l  = linw + l * HCC * CC;
        const float* lb_l  = linb + l * CC;
        const float* l2w_l = ln2w + l * CC;
        const float* l2b_l = ln2b + l * CC;

        k_linlr<<<(NN + 31) / 32, 128>>>(Wl_l, bl_l, Wr_l, br_l);
        k_gat<<<gatBlocks, 256>>>(We_l, att_l, gb_l);
        k_lin2<<<gatBlocks, 256>>>(gb_l, l1w_l, l1b_l, lw_l, lb_l, l2w_l, l2b_l, out);
    }
}